// round 12
// baseline (speedup 1.0000x reference)
#include <cuda_runtime.h>
#include <cuda_fp16.h>
#include <cstdint>

#define NSITES 1000000
#define KVOL 27
#define MTILE 128
#define NTILES ((NSITES + MTILE - 1) / MTILE)  // 7813
#define EPSV 1e-5f
#define NST 4  // pipeline stages

// ---------------- scratch (device globals; no allocation allowed) ----------
__device__ __half d_h1h[(size_t)NSITES * 32];  // conv1 raw out -> BN1 in place
__device__ __half d_xh[(size_t)NSITES * 16];   // feats as half
__device__ __half d_wT1[KVOL * 16 * 32];       // WT[k][cout][cin] half
__device__ __half d_wT2[KVOL * 32 * 32];
__device__ float d_part[(size_t)NTILES * 64];  // per-tile [sum(32), sumsq(32)]
__device__ float d_sb1[64];
__device__ float d_sb2[64];

// ---------------- helpers ---------------------------------------------------
static __device__ __forceinline__ uint32_t s2u(const void* p) {
    return (uint32_t)__cvta_generic_to_shared(p);
}
static __device__ __forceinline__ void cp16(uint32_t dst, const void* src,
                                            uint32_t srcsize) {
    asm volatile("cp.async.ca.shared.global [%0], [%1], 16, %2;\n" ::"r"(dst),
                 "l"(src), "r"(srcsize));
}
static __device__ __forceinline__ void cp_commit() {
    asm volatile("cp.async.commit_group;\n" ::: "memory");
}
template <int N>
static __device__ __forceinline__ void cp_wait() {
    asm volatile("cp.async.wait_group %0;\n" ::"n"(N) : "memory");
}
// mma.sync m16n8k16 fp16->fp32
static __device__ __forceinline__ void mma_f16(float* d, uint32_t a0,
                                               uint32_t a1, uint32_t a2,
                                               uint32_t a3, uint32_t b0,
                                               uint32_t b1) {
    asm volatile(
        "mma.sync.aligned.m16n8k16.row.col.f32.f16.f16.f32 "
        "{%0,%1,%2,%3},{%4,%5,%6,%7},{%8,%9},{%0,%1,%2,%3};"
        : "+f"(d[0]), "+f"(d[1]), "+f"(d[2]), "+f"(d[3])
        : "r"(a0), "r"(a1), "r"(a2), "r"(a3), "r"(b0), "r"(b1));
}
// ldmatrix x4: four 8-row x 16B submatrices
static __device__ __forceinline__ void ldsm4(uint32_t& r0, uint32_t& r1,
                                             uint32_t& r2, uint32_t& r3,
                                             uint32_t addr) {
    asm volatile(
        "ldmatrix.sync.aligned.m8n8.x4.shared.b16 {%0,%1,%2,%3}, [%4];"
        : "=r"(r0), "=r"(r1), "=r"(r2), "=r"(r3)
        : "r"(addr));
}

// ---------------- feats -> half ---------------------------------------------
__global__ __launch_bounds__(256) void prep_x(const float* __restrict__ X) {
    const long long i = (long long)blockIdx.x * 256 + threadIdx.x;  // float4 idx
    const float4 v = reinterpret_cast<const float4*>(X)[i];
    __half2* o = reinterpret_cast<__half2*>(d_xh);
    o[2 * i + 0] = __floats2half2_rn(v.x, v.y);
    o[2 * i + 1] = __floats2half2_rn(v.z, v.w);
}

// ---------------- weight transpose -> half ----------------------------------
// W[k][cin][cout] -> WT[k][cout][cin] half
__global__ void prep_w(const float* __restrict__ W, __half* __restrict__ dst,
                       int cin) {
    const int k = blockIdx.x;
    for (int e = threadIdx.x; e < cin * 32; e += 256) {
        const int i = e / 32;
        const int c = e % 32;
        dst[((size_t)k * 32 + c) * cin + i] =
            __float2half_rn(W[((size_t)k * cin + i) * 32 + c]);
    }
}

// ---------------- fp16 mma gather-conv --------------------------------------
// 256 thr / 8 warps; warp w: one m16 tile (16 sites) x 32 couts.
// 4-stage cp.async ring, depth-3 prefetch, idx prefetched one iter early,
// ONE barrier per iteration (4-ring makes the post-compute barrier redundant).
// nm read directly (CTA slice is 13.8KB -> L1-resident after first k).
// OH=1: store half (conv1), OH=0: store float (conv2).
template <int CIN, int OH>
__global__ __launch_bounds__(256) void conv_mma(const __half* __restrict__ X,
                                                const int* __restrict__ nm,
                                                const __half* __restrict__ WT,
                                                void* __restrict__ Yv) {
    constexpr int NK = CIN / 16;      // K-steps per offset (2 or 1)
    constexpr int CHA = CIN / 8;      // 16B chunks per row (4 or 2)
    constexpr int STR = CIN + 8;      // padded row stride (halfs)
    constexpr int STRB = STR * 2;     // bytes
    constexpr int STAGE = 160 * STR;  // halfs per stage (128 A + 32 B rows)
    constexpr int IDXN = (CHA + 1) / 2;  // gather rows per thread (2 or 1)

    extern __shared__ __half smem[];
    float* const red = reinterpret_cast<float*>(smem);  // reused post-loop

    const int t = threadIdx.x;
    const int w = t >> 5;     // 0..7
    const int lane = t & 31;
    const int g = lane >> 2;  // groupID
    const int ti = lane & 3;  // thread-in-group
    const int siteBase = blockIdx.x * MTILE;

    // ldmatrix per-lane base offsets (bytes)
    const int lr = lane & 7;
    const int sel = lane >> 3;
    const uint32_t aoff =
        (uint32_t)((w * 16 + (sel & 1) * 8 + lr) * STRB + ((sel & 2) ? 16 : 0));
    const uint32_t boff =
        (uint32_t)((((sel >> 1) & 1) * 8 + lr) * STRB + (sel & 1) * 16);

    auto load_idx = [&](int k, int* nidx) {
#pragma unroll
        for (int i = 0; i < IDXN; i++) {
            const int f = i * 256 + t;
            const int row = f / CHA;
            const int gsite = siteBase + row;
            nidx[i] =
                (gsite < NSITES) ? __ldg(nm + (size_t)gsite * KVOL + k) : -1;
        }
    };
    auto do_issue = [&](int k, int s, const int* nidx) {
        __half* const As = smem + s * STAGE;
        __half* const Bs = As + 128 * STR;
        const __half* wsrc = WT + (size_t)k * CIN * 32;
        if (t < 32 * CHA) {
            const int row = t / CHA;
            const int ch = t % CHA;
            cp16(s2u(Bs + row * STR + ch * 8), wsrc + t * 8, 16);
        }
#pragma unroll
        for (int i = 0; i < IDXN; i++) {
            const int f = i * 256 + t;
            const int row = f / CHA;
            const int ch = f % CHA;
            const int idx = nidx[i];
            const __half* src =
                X + ((idx >= 0) ? (size_t)idx * CIN : 0) + ch * 8;
            cp16(s2u(As + row * STR + ch * 8), src, (idx >= 0) ? 16u : 0u);
        }
    };

    float acc[4][4];
#pragma unroll
    for (int n = 0; n < 4; n++)
#pragma unroll
        for (int r = 0; r < 4; r++) acc[n][r] = 0.f;

    {
        int pidx[IDXN];
        load_idx(0, pidx);
        do_issue(0, 0, pidx);
        cp_commit();
        load_idx(1, pidx);
        do_issue(1, 1, pidx);
        cp_commit();
        load_idx(2, pidx);
        do_issue(2, 2, pidx);
        cp_commit();
    }

#pragma unroll 1
    for (int k = 0; k < KVOL; k++) {
        int nidx[IDXN];
        if (k + 3 < KVOL) load_idx(k + 3, nidx);  // overlaps wait + compute
        cp_wait<2>();  // retires group k (uniform dummy commits)
        __syncthreads();

        const __half* As = smem + (k & 3) * STAGE;
        const uint32_t abase = s2u(As) + aoff;
        const uint32_t bbase = s2u(As + 128 * STR) + boff;
#pragma unroll
        for (int ks = 0; ks < NK; ks++) {
            uint32_t bf[4][2];
            ldsm4(bf[0][0], bf[0][1], bf[1][0], bf[1][1],
                  bbase + (uint32_t)(ks * 32));
            ldsm4(bf[2][0], bf[2][1], bf[3][0], bf[3][1],
                  bbase + (uint32_t)(16 * STRB + ks * 32));
            uint32_t a0, a1, a2, a3;
            ldsm4(a0, a1, a2, a3, abase + (uint32_t)(ks * 32));
#pragma unroll
            for (int n = 0; n < 4; n++)
                mma_f16(acc[n], a0, a1, a2, a3, bf[n][0], bf[n][1]);
        }
        // No second barrier: issue targets stage (k+3)&3 = (k-1)&3, whose
        // last readers finished before this iteration's top barrier.
        if (k + 3 < KVOL) do_issue(k + 3, (k + 3) & 3, nidx);
        cp_commit();  // possibly-empty group keeps wait<2> ledger exact
    }

    // ---- store: thread holds rows {w*16+g, +8}, cols {n*8+2ti, +1} ----
#pragma unroll
    for (int rr = 0; rr < 2; rr++) {
        const int row = w * 16 + rr * 8 + g;
        const int site = siteBase + row;
        if (site < NSITES) {
            if (OH) {
                __half* yr = (__half*)Yv + (size_t)site * 32 + 2 * ti;
#pragma unroll
                for (int n = 0; n < 4; n++)
                    *reinterpret_cast<__half2*>(yr + n * 8) =
                        __floats2half2_rn(acc[n][rr * 2], acc[n][rr * 2 + 1]);
            } else {
                float* yr = (float*)Yv + (size_t)site * 32 + 2 * ti;
#pragma unroll
                for (int n = 0; n < 4; n++)
                    *reinterpret_cast<float2*>(yr + n * 8) =
                        make_float2(acc[n][rr * 2], acc[n][rr * 2 + 1]);
            }
        }
    }

    // ---- BN partial stats (tail rows zero by construction) ----
    float s[8], q[8];
#pragma unroll
    for (int i = 0; i < 8; i++) {
        s[i] = 0.f;
        q[i] = 0.f;
    }
#pragma unroll
    for (int n = 0; n < 4; n++)
#pragma unroll
        for (int rr = 0; rr < 2; rr++)
#pragma unroll
            for (int e = 0; e < 2; e++) {
                const float v = acc[n][rr * 2 + e];
                s[n * 2 + e] += v;
                q[n * 2 + e] += v * v;
            }
#pragma unroll
    for (int i = 0; i < 8; i++) {
#pragma unroll
        for (int o = 4; o <= 16; o <<= 1) {
            s[i] += __shfl_xor_sync(0xffffffffu, s[i], o);
            q[i] += __shfl_xor_sync(0xffffffffu, q[i], o);
        }
    }
    __syncthreads();  // stage smem free for reduction
    if (g == 0) {
#pragma unroll
        for (int i = 0; i < 8; i++) {
            const int col = (i / 2) * 8 + 2 * ti + (i % 2);
            red[w * 64 + col] = s[i];
            red[w * 64 + 32 + col] = q[i];
        }
    }
    __syncthreads();
    if (t < 64) {
        float ss = 0.f;
#pragma unroll
        for (int wi = 0; wi < 8; wi++) ss += red[wi * 64 + t];
        d_part[(size_t)blockIdx.x * 64 + t] = ss;
    }
}

// ---------------- finalize BN stats -> scale/bias --------------------------
__global__ void finalize_kernel(const float* __restrict__ gamma,
                                const float* __restrict__ beta,
                                float* __restrict__ sb, int nb) {
    const int c = blockIdx.x;  // 0..31
    float s = 0.f, q = 0.f;
    for (int b = threadIdx.x; b < nb; b += 256) {
        s += d_part[(size_t)b * 64 + c];
        q += d_part[(size_t)b * 64 + 32 + c];
    }
    __shared__ float ss[8], qs[8];
    const int lane = threadIdx.x & 31;
    const int wrp = threadIdx.x >> 5;
#pragma unroll
    for (int o = 16; o > 0; o >>= 1) {
        s += __shfl_down_sync(0xffffffffu, s, o);
        q += __shfl_down_sync(0xffffffffu, q, o);
    }
    if (lane == 0) {
        ss[wrp] = s;
        qs[wrp] = q;
    }
    __syncthreads();
    if (threadIdx.x == 0) {
        float S = 0.f, Q = 0.f;
#pragma unroll
        for (int w = 0; w < 8; w++) {
            S += ss[w];
            Q += qs[w];
        }
        const float inv_n = 1.0f / (float)NSITES;
        float mean = S * inv_n;
        float var = Q * inv_n - mean * mean;
        float scale = gamma[c] * rsqrtf(var + EPSV);
        sb[c] = scale;
        sb[32 + c] = beta[c] - mean * scale;
    }
}

// ---------------- BN + ReLU on half, in place (conv1 -> conv2 input) --------
__global__ __launch_bounds__(256) void bnrelu_h_kernel(
    __half* __restrict__ HY, const float* __restrict__ sb) {
    __shared__ float sc[32], bi[32];
    if (threadIdx.x < 32) {
        sc[threadIdx.x] = sb[threadIdx.x];
        bi[threadIdx.x] = sb[32 + threadIdx.x];
    }
    __syncthreads();
    const long long i = (long long)blockIdx.x * 256 + threadIdx.x;  // uint4 idx
    uint4 v = reinterpret_cast<uint4*>(HY)[i];
    const int c0 = (int)((i * 8) & 31);
    uint32_t* vw = reinterpret_cast<uint32_t*>(&v);
#pragma unroll
    for (int j = 0; j < 4; j++) {
        __half2 h = *reinterpret_cast<__half2*>(&vw[j]);
        float2 f = __half22float2(h);
        f.x = fmaxf(0.f, fmaf(f.x, sc[c0 + 2 * j], bi[c0 + 2 * j]));
        f.y = fmaxf(0.f, fmaf(f.y, sc[c0 + 2 * j + 1], bi[c0 + 2 * j + 1]));
        h = __floats2half2_rn(f.x, f.y);
        vw[j] = *reinterpret_cast<uint32_t*>(&h);
    }
    reinterpret_cast<uint4*>(HY)[i] = v;
}

// ---------------- BN + ReLU on fp32, in place (final output) ----------------
__global__ __launch_bounds__(256) void bnrelu_f_kernel(
    float* __restrict__ Y, const float* __restrict__ sb) {
    __shared__ float sc[32], bi[32];
    if (threadIdx.x < 32) {
        sc[threadIdx.x] = sb[threadIdx.x];
        bi[threadIdx.x] = sb[32 + threadIdx.x];
    }
    __syncthreads();
    const long long i = (long long)blockIdx.x * 256 + threadIdx.x;  // float4 idx
    float4 v = reinterpret_cast<const float4*>(Y)[i];
    const int c0 = (int)((i * 4) & 31);
    v.x = fmaxf(0.f, fmaf(v.x, sc[c0 + 0], bi[c0 + 0]));
    v.y = fmaxf(0.f, fmaf(v.y, sc[c0 + 1], bi[c0 + 1]));
    v.z = fmaxf(0.f, fmaf(v.z, sc[c0 + 2], bi[c0 + 2]));
    v.w = fmaxf(0.f, fmaf(v.w, sc[c0 + 3], bi[c0 + 3]));
    reinterpret_cast<float4*>(Y)[i] = v;
}

// ---------------- launch ----------------------------------------------------
extern "C" void kernel_launch(void* const* d_in, const int* in_sizes, int n_in,
                              void* d_out, int out_size) {
    const float* feats = (const float*)d_in[0];
    const int* nm = (const int*)d_in[1];
    const float* W1 = (const float*)d_in[2];
    const float* gamma1 = (const float*)d_in[3];
    const float* beta1 = (const float*)d_in[4];
    const float* W2 = (const float*)d_in[5];
    const float* gamma2 = (const float*)d_in[6];
    const float* beta2 = (const float*)d_in[7];
    float* out = (float*)d_out;

    const int smem1 = NST * 160 * (16 + 8) * 2;  // 30720 B
    const int smem2 = NST * 160 * (32 + 8) * 2;  // 51200 B
    cudaFuncSetAttribute(conv_mma<16, 1>,
                         cudaFuncAttributeMaxDynamicSharedMemorySize, smem1);
    cudaFuncSetAttribute(conv_mma<32, 0>,
                         cudaFuncAttributeMaxDynamicSharedMemorySize, smem2);

    void* p;
    cudaGetSymbolAddress(&p, d_h1h);
    __half* h1h = (__half*)p;
    cudaGetSymbolAddress(&p, d_xh);
    __half* xh = (__half*)p;
    cudaGetSymbolAddress(&p, d_wT1);
    __half* wT1 = (__half*)p;
    cudaGetSymbolAddress(&p, d_wT2);
    __half* wT2 = (__half*)p;
    cudaGetSymbolAddress(&p, d_sb1);
    float* sb1 = (float*)p;
    cudaGetSymbolAddress(&p, d_sb2);
    float* sb2 = (float*)p;

    const int ewf_blocks = (int)(((long long)NSITES * 32 / 4) / 256);  // 31250
    const int ewh_blocks = (int)(((long long)NSITES * 32 / 8) / 256);  // 15625
    const int px_blocks = (int)(((long long)NSITES * 16 / 4) / 256);   // 15625

    prep_x<<<px_blocks, 256>>>(feats);
    prep_w<<<KVOL, 256>>>(W1, wT1, 16);
    prep_w<<<KVOL, 256>>>(W2, wT2, 32);

    conv_mma<16, 1><<<NTILES, 256, smem1>>>(xh, nm, wT1, h1h);
    finalize_kernel<<<32, 256>>>(gamma1, beta1, sb1, NTILES);
    bnrelu_h_kernel<<<ewh_blocks, 256>>>(h1h, sb1);

    conv_mma<32, 0><<<NTILES, 256, smem2>>>(h1h, nm, wT2, out);
    finalize_kernel<<<32, 256>>>(gamma2, beta2, sb2, NTILES);
    bnrelu_f_kernel<<<ewf_blocks, 256>>>(out, sb2);
}

// round 15
// speedup vs baseline: 1.0843x; 1.0843x over previous
#include <cuda_runtime.h>
#include <cuda_fp16.h>
#include <cstdint>

#define NSITES 1000000
#define KVOL 27
#define MTILE 128
#define NTILES ((NSITES + MTILE - 1) / MTILE)  // 7813
#define EPSV 1e-5f
#define NST 4  // pipeline stages

// ---------------- scratch (device globals; no allocation allowed) ----------
__device__ __half d_h1h[(size_t)NSITES * 32];  // conv1 raw out -> BN1 in place
__device__ __half d_xh[(size_t)NSITES * 16];   // feats as half
__device__ int d_nmT[(size_t)KVOL * NSITES];   // transposed neighbor map
__device__ __half d_wT1[KVOL * 16 * 32];       // WT[k][cout][cin] half
__device__ __half d_wT2[KVOL * 32 * 32];
__device__ float d_part[(size_t)NTILES * 64];  // per-tile [sum(32), sumsq(32)]
__device__ float d_sb1[64];
__device__ float d_sb2[64];

// ---------------- helpers ---------------------------------------------------
static __device__ __forceinline__ uint32_t s2u(const void* p) {
    return (uint32_t)__cvta_generic_to_shared(p);
}
static __device__ __forceinline__ void cp16(uint32_t dst, const void* src,
                                            uint32_t srcsize) {
    asm volatile("cp.async.ca.shared.global [%0], [%1], 16, %2;\n" ::"r"(dst),
                 "l"(src), "r"(srcsize));
}
static __device__ __forceinline__ void cp_commit() {
    asm volatile("cp.async.commit_group;\n" ::: "memory");
}
template <int N>
static __device__ __forceinline__ void cp_wait() {
    asm volatile("cp.async.wait_group %0;\n" ::"n"(N) : "memory");
}
// mma.sync m16n8k16 fp16->fp32
static __device__ __forceinline__ void mma_f16(float* d, uint32_t a0,
                                               uint32_t a1, uint32_t a2,
                                               uint32_t a3, uint32_t b0,
                                               uint32_t b1) {
    asm volatile(
        "mma.sync.aligned.m16n8k16.row.col.f32.f16.f16.f32 "
        "{%0,%1,%2,%3},{%4,%5,%6,%7},{%8,%9},{%0,%1,%2,%3};"
        : "+f"(d[0]), "+f"(d[1]), "+f"(d[2]), "+f"(d[3])
        : "r"(a0), "r"(a1), "r"(a2), "r"(a3), "r"(b0), "r"(b1));
}
// ldmatrix x4: four 8-row x 16B submatrices
static __device__ __forceinline__ void ldsm4(uint32_t& r0, uint32_t& r1,
                                             uint32_t& r2, uint32_t& r3,
                                             uint32_t addr) {
    asm volatile(
        "ldmatrix.sync.aligned.m8n8.x4.shared.b16 {%0,%1,%2,%3}, [%4];"
        : "=r"(r0), "=r"(r1), "=r"(r2), "=r"(r3)
        : "r"(addr));
}

// ---------------- neighbor-map transpose ------------------------------------
__global__ __launch_bounds__(256) void transpose_nm(const int* __restrict__ nm) {
    __shared__ int tb[256 * KVOL];
    const int base = blockIdx.x * 256;
    const int nrows = min(256, NSITES - base);
    const int n = nrows * KVOL;
    const long long start = (long long)base * KVOL;
    for (int i = threadIdx.x; i < n; i += 256) tb[i] = nm[start + i];
    __syncthreads();
    const int t = threadIdx.x;
    if (base + t < NSITES) {
#pragma unroll
        for (int k = 0; k < KVOL; k++)
            d_nmT[(size_t)k * NSITES + base + t] = tb[t * KVOL + k];
    }
}

// ---------------- feats -> half ---------------------------------------------
__global__ __launch_bounds__(256) void prep_x(const float* __restrict__ X) {
    const long long i = (long long)blockIdx.x * 256 + threadIdx.x;  // float4 idx
    const float4 v = reinterpret_cast<const float4*>(X)[i];
    __half2* o = reinterpret_cast<__half2*>(d_xh);
    o[2 * i + 0] = __floats2half2_rn(v.x, v.y);
    o[2 * i + 1] = __floats2half2_rn(v.z, v.w);
}

// ---------------- weight transpose -> half ----------------------------------
// W[k][cin][cout] -> WT[k][cout][cin] half
__global__ void prep_w(const float* __restrict__ W, __half* __restrict__ dst,
                       int cin) {
    const int k = blockIdx.x;
    for (int e = threadIdx.x; e < cin * 32; e += 256) {
        const int i = e / 32;
        const int c = e % 32;
        dst[((size_t)k * 32 + c) * cin + i] =
            __float2half_rn(W[((size_t)k * cin + i) * 32 + c]);
    }
}

// ---------------- fp16 mma gather-conv (R11 loop, OH output) ----------------
// 256 thr / 8 warps; warp w: one m16 tile (16 sites) x 32 couts.
// 4-stage cp.async ring, depth-3 prefetch (dummy commits keep wait uniform).
// OH=1: store half (conv1), OH=0: store float (conv2).
template <int CIN, int OH>
__global__ __launch_bounds__(256) void conv_mma(const __half* __restrict__ X,
                                                const __half* __restrict__ WT,
                                                void* __restrict__ Yv) {
    constexpr int NK = CIN / 16;      // K-steps per offset (2 or 1)
    constexpr int CHA = CIN / 8;      // 16B chunks per row (4 or 2)
    constexpr int STR = CIN + 8;      // padded row stride (halfs)
    constexpr int STRB = STR * 2;     // bytes
    constexpr int STAGE = 160 * STR;  // halfs per stage (128 A + 32 B rows)

    extern __shared__ __half smem[];
    float* const red = reinterpret_cast<float*>(smem);  // reused post-loop

    const int t = threadIdx.x;
    const int w = t >> 5;     // 0..7
    const int lane = t & 31;
    const int g = lane >> 2;  // groupID
    const int ti = lane & 3;  // thread-in-group
    const int siteBase = blockIdx.x * MTILE;

    // ldmatrix per-lane base offsets (bytes)
    const int lr = lane & 7;
    const int sel = lane >> 3;
    const uint32_t aoff =
        (uint32_t)((w * 16 + (sel & 1) * 8 + lr) * STRB + ((sel & 2) ? 16 : 0));
    const uint32_t boff =
        (uint32_t)((((sel >> 1) & 1) * 8 + lr) * STRB + (sel & 1) * 16);

    auto issue = [&](int k, int s) {
        __half* const As = smem + s * STAGE;
        __half* const Bs = As + 128 * STR;
        // B: WT slice [32][CIN] half -> padded rows
        const __half* wsrc = WT + (size_t)k * CIN * 32;
        if (t < 32 * CHA) {
            const int row = t / CHA;
            const int ch = t % CHA;
            cp16(s2u(Bs + row * STR + ch * 8), wsrc + t * 8, 16);
        }
        // A: gathered rows (CHA 16B chunks each), 128*CHA ops over 256 thr
        const int* nmk = d_nmT + (size_t)k * NSITES;
#pragma unroll
        for (int f = t; f < 128 * CHA; f += 256) {
            const int row = f / CHA;
            const int ch = f % CHA;
            const int gsite = siteBase + row;
            const int idx = (gsite < NSITES) ? nmk[gsite] : -1;
            const __half* src =
                X + ((idx >= 0) ? (size_t)idx * CIN : 0) + ch * 8;
            cp16(s2u(As + row * STR + ch * 8), src, (idx >= 0) ? 16u : 0u);
        }
    };

    float acc[4][4];
#pragma unroll
    for (int n = 0; n < 4; n++)
#pragma unroll
        for (int r = 0; r < 4; r++) acc[n][r] = 0.f;

    issue(0, 0);
    cp_commit();
    issue(1, 1);
    cp_commit();
    issue(2, 2);
    cp_commit();

#pragma unroll 1
    for (int k = 0; k < KVOL; k++) {
        cp_wait<2>();  // retires group k (dummy commits keep count uniform)
        __syncthreads();

        const __half* As = smem + (k & 3) * STAGE;
        const uint32_t abase = s2u(As) + aoff;
        const uint32_t bbase = s2u(As + 128 * STR) + boff;
#pragma unroll
        for (int ks = 0; ks < NK; ks++) {
            uint32_t bf[4][2];
            ldsm4(bf[0][0], bf[0][1], bf[1][0], bf[1][1],
                  bbase + (uint32_t)(ks * 32));
            ldsm4(bf[2][0], bf[2][1], bf[3][0], bf[3][1],
                  bbase + (uint32_t)(16 * STRB + ks * 32));
            uint32_t a0, a1, a2, a3;
            ldsm4(a0, a1, a2, a3, abase + (uint32_t)(ks * 32));
#pragma unroll
            for (int n = 0; n < 4; n++)
                mma_f16(acc[n], a0, a1, a2, a3, bf[n][0], bf[n][1]);
        }
        __syncthreads();
        if (k + 3 < KVOL) issue(k + 3, (k + 3) & 3);
        cp_commit();  // possibly-empty group: keeps wait<2> ledger exact
    }

    // ---- store: thread holds rows {w*16+g, +8}, cols {n*8+2ti, +1} ----
#pragma unroll
    for (int rr = 0; rr < 2; rr++) {
        const int row = w * 16 + rr * 8 + g;
        const int site = siteBase + row;
        if (site < NSITES) {
            if (OH) {
                __half* yr = (__half*)Yv + (size_t)site * 32 + 2 * ti;
#pragma unroll
                for (int n = 0; n < 4; n++)
                    *reinterpret_cast<__half2*>(yr + n * 8) =
                        __floats2half2_rn(acc[n][rr * 2], acc[n][rr * 2 + 1]);
            } else {
                float* yr = (float*)Yv + (size_t)site * 32 + 2 * ti;
#pragma unroll
                for (int n = 0; n < 4; n++)
                    *reinterpret_cast<float2*>(yr + n * 8) =
                        make_float2(acc[n][rr * 2], acc[n][rr * 2 + 1]);
            }
        }
    }

    // ---- BN partial stats (tail rows zero by construction) ----
    float s[8], q[8];
#pragma unroll
    for (int i = 0; i < 8; i++) {
        s[i] = 0.f;
        q[i] = 0.f;
    }
#pragma unroll
    for (int n = 0; n < 4; n++)
#pragma unroll
        for (int rr = 0; rr < 2; rr++)
#pragma unroll
            for (int e = 0; e < 2; e++) {
                const float v = acc[n][rr * 2 + e];
                s[n * 2 + e] += v;
                q[n * 2 + e] += v * v;
            }
#pragma unroll
    for (int i = 0; i < 8; i++) {
#pragma unroll
        for (int o = 4; o <= 16; o <<= 1) {
            s[i] += __shfl_xor_sync(0xffffffffu, s[i], o);
            q[i] += __shfl_xor_sync(0xffffffffu, q[i], o);
        }
    }
    __syncthreads();  // stage smem free for reduction
    if (g == 0) {
#pragma unroll
        for (int i = 0; i < 8; i++) {
            const int col = (i / 2) * 8 + 2 * ti + (i % 2);
            red[w * 64 + col] = s[i];
            red[w * 64 + 32 + col] = q[i];
        }
    }
    __syncthreads();
    if (t < 64) {
        float ss = 0.f;
#pragma unroll
        for (int wi = 0; wi < 8; wi++) ss += red[wi * 64 + t];
        d_part[(size_t)blockIdx.x * 64 + t] = ss;
    }
}

// ---------------- finalize BN stats -> scale/bias --------------------------
__global__ void finalize_kernel(const float* __restrict__ gamma,
                                const float* __restrict__ beta,
                                float* __restrict__ sb, int nb) {
    const int c = blockIdx.x;  // 0..31
    float s = 0.f, q = 0.f;
    for (int b = threadIdx.x; b < nb; b += 256) {
        s += d_part[(size_t)b * 64 + c];
        q += d_part[(size_t)b * 64 + 32 + c];
    }
    __shared__ float ss[8], qs[8];
    const int lane = threadIdx.x & 31;
    const int wrp = threadIdx.x >> 5;
#pragma unroll
    for (int o = 16; o > 0; o >>= 1) {
        s += __shfl_down_sync(0xffffffffu, s, o);
        q += __shfl_down_sync(0xffffffffu, q, o);
    }
    if (lane == 0) {
        ss[wrp] = s;
        qs[wrp] = q;
    }
    __syncthreads();
    if (threadIdx.x == 0) {
        float S = 0.f, Q = 0.f;
#pragma unroll
        for (int w = 0; w < 8; w++) {
            S += ss[w];
            Q += qs[w];
        }
        const float inv_n = 1.0f / (float)NSITES;
        float mean = S * inv_n;
        float var = Q * inv_n - mean * mean;
        float scale = gamma[c] * rsqrtf(var + EPSV);
        sb[c] = scale;
        sb[32 + c] = beta[c] - mean * scale;
    }
}

// ---------------- BN + ReLU on half, in place (conv1 -> conv2 input) --------
__global__ __launch_bounds__(256) void bnrelu_h_kernel(
    __half* __restrict__ HY, const float* __restrict__ sb) {
    __shared__ float sc[32], bi[32];
    if (threadIdx.x < 32) {
        sc[threadIdx.x] = sb[threadIdx.x];
        bi[threadIdx.x] = sb[32 + threadIdx.x];
    }
    __syncthreads();
    const long long i = (long long)blockIdx.x * 256 + threadIdx.x;  // uint4 idx
    uint4 v = reinterpret_cast<uint4*>(HY)[i];
    const int c0 = (int)((i * 8) & 31);
    uint32_t* vw = reinterpret_cast<uint32_t*>(&v);
#pragma unroll
    for (int j = 0; j < 4; j++) {
        __half2 h = *reinterpret_cast<__half2*>(&vw[j]);
        float2 f = __half22float2(h);
        f.x = fmaxf(0.f, fmaf(f.x, sc[c0 + 2 * j], bi[c0 + 2 * j]));
        f.y = fmaxf(0.f, fmaf(f.y, sc[c0 + 2 * j + 1], bi[c0 + 2 * j + 1]));
        h = __floats2half2_rn(f.x, f.y);
        vw[j] = *reinterpret_cast<uint32_t*>(&h);
    }
    reinterpret_cast<uint4*>(HY)[i] = v;
}

// ---------------- BN + ReLU on fp32, in place (final output) ----------------
__global__ __launch_bounds__(256) void bnrelu_f_kernel(
    float* __restrict__ Y, const float* __restrict__ sb) {
    __shared__ float sc[32], bi[32];
    if (threadIdx.x < 32) {
        sc[threadIdx.x] = sb[threadIdx.x];
        bi[threadIdx.x] = sb[32 + threadIdx.x];
    }
    __syncthreads();
    const long long i = (long long)blockIdx.x * 256 + threadIdx.x;  // float4 idx
    float4 v = reinterpret_cast<const float4*>(Y)[i];
    const int c0 = (int)((i * 4) & 31);
    v.x = fmaxf(0.f, fmaf(v.x, sc[c0 + 0], bi[c0 + 0]));
    v.y = fmaxf(0.f, fmaf(v.y, sc[c0 + 1], bi[c0 + 1]));
    v.z = fmaxf(0.f, fmaf(v.z, sc[c0 + 2], bi[c0 + 2]));
    v.w = fmaxf(0.f, fmaf(v.w, sc[c0 + 3], bi[c0 + 3]));
    reinterpret_cast<float4*>(Y)[i] = v;
}

// ---------------- launch ----------------------------------------------------
extern "C" void kernel_launch(void* const* d_in, const int* in_sizes, int n_in,
                              void* d_out, int out_size) {
    const float* feats = (const float*)d_in[0];
    const int* nm = (const int*)d_in[1];
    const float* W1 = (const float*)d_in[2];
    const float* gamma1 = (const float*)d_in[3];
    const float* beta1 = (const float*)d_in[4];
    const float* W2 = (const float*)d_in[5];
    const float* gamma2 = (const float*)d_in[6];
    const float* beta2 = (const float*)d_in[7];
    float* out = (float*)d_out;

    const int smem1 = NST * 160 * (16 + 8) * 2;  // 30720 B
    const int smem2 = NST * 160 * (32 + 8) * 2;  // 51200 B
    cudaFuncSetAttribute(conv_mma<16, 1>,
                         cudaFuncAttributeMaxDynamicSharedMemorySize, smem1);
    cudaFuncSetAttribute(conv_mma<32, 0>,
                         cudaFuncAttributeMaxDynamicSharedMemorySize, smem2);

    void* p;
    cudaGetSymbolAddress(&p, d_h1h);
    __half* h1h = (__half*)p;
    cudaGetSymbolAddress(&p, d_xh);
    __half* xh = (__half*)p;
    cudaGetSymbolAddress(&p, d_wT1);
    __half* wT1 = (__half*)p;
    cudaGetSymbolAddress(&p, d_wT2);
    __half* wT2 = (__half*)p;
    cudaGetSymbolAddress(&p, d_sb1);
    float* sb1 = (float*)p;
    cudaGetSymbolAddress(&p, d_sb2);
    float* sb2 = (float*)p;

    const int ewf_blocks = (int)(((long long)NSITES * 32 / 4) / 256);  // 31250
    const int ewh_blocks = (int)(((long long)NSITES * 32 / 8) / 256);  // 15625
    const int px_blocks = (int)(((long long)NSITES * 16 / 4) / 256);   // 15625
    const int tr_blocks = (NSITES + 255) / 256;                        // 3907

    transpose_nm<<<tr_blocks, 256>>>(nm);
    prep_x<<<px_blocks, 256>>>(feats);
    prep_w<<<KVOL, 256>>>(W1, wT1, 16);
    prep_w<<<KVOL, 256>>>(W2, wT2, 32);

    conv_mma<16, 1><<<NTILES, 256, smem1>>>(xh, wT1, h1h);
    finalize_kernel<<<32, 256>>>(gamma1, beta1, sb1, NTILES);
    bnrelu_h_kernel<<<ewh_blocks, 256>>>(h1h, sb1);

    conv_mma<32, 0><<<NTILES, 256, smem2>>>(h1h, wT2, out);
    finalize_kernel<<<32, 256>>>(gamma2, beta2, sb2, NTILES);
    bnrelu_f_kernel<<<ewf_blocks, 256>>>(out, sb2);
}

// round 16
// speedup vs baseline: 1.1534x; 1.0637x over previous
#include <cuda_runtime.h>
#include <cuda_fp16.h>
#include <cstdint>

#define NSITES 1000000
#define KVOL 27
#define MTILE 128
#define NTILES ((NSITES + MTILE - 1) / MTILE)  // 7813
#define EPSV 1e-5f
#define NST 4  // pipeline stages

// ---------------- scratch (device globals; no allocation allowed) ----------
__device__ __half d_h1h[(size_t)NSITES * 32];  // conv1 raw out -> BN1 in place
__device__ __half d_xh[(size_t)NSITES * 16];   // feats as half
__device__ int d_nmT[(size_t)KVOL * NSITES];   // transposed neighbor map
__device__ __half d_wT1[KVOL * 16 * 32];       // WT[k][cout][cin] half
__device__ __half d_wT2[KVOL * 32 * 32];
__device__ float d_part[(size_t)NTILES * 64];  // per-tile [sum(32), sumsq(32)]
__device__ float d_sb1[64];
__device__ float d_sb2[64];

// ---------------- helpers ---------------------------------------------------
static __device__ __forceinline__ uint32_t s2u(const void* p) {
    return (uint32_t)__cvta_generic_to_shared(p);
}
static __device__ __forceinline__ void cp16(uint32_t dst, const void* src,
                                            uint32_t srcsize) {
    asm volatile("cp.async.ca.shared.global [%0], [%1], 16, %2;\n" ::"r"(dst),
                 "l"(src), "r"(srcsize));
}
static __device__ __forceinline__ void cp_commit() {
    asm volatile("cp.async.commit_group;\n" ::: "memory");
}
template <int N>
static __device__ __forceinline__ void cp_wait() {
    asm volatile("cp.async.wait_group %0;\n" ::"n"(N) : "memory");
}
// mma.sync m16n8k16 fp16->fp32
static __device__ __forceinline__ void mma_f16(float* d, uint32_t a0,
                                               uint32_t a1, uint32_t a2,
                                               uint32_t a3, uint32_t b0,
                                               uint32_t b1) {
    asm volatile(
        "mma.sync.aligned.m16n8k16.row.col.f32.f16.f16.f32 "
        "{%0,%1,%2,%3},{%4,%5,%6,%7},{%8,%9},{%0,%1,%2,%3};"
        : "+f"(d[0]), "+f"(d[1]), "+f"(d[2]), "+f"(d[3])
        : "r"(a0), "r"(a1), "r"(a2), "r"(a3), "r"(b0), "r"(b1));
}
// ldmatrix x4: four 8-row x 16B submatrices
static __device__ __forceinline__ void ldsm4(uint32_t& r0, uint32_t& r1,
                                             uint32_t& r2, uint32_t& r3,
                                             uint32_t addr) {
    asm volatile(
        "ldmatrix.sync.aligned.m8n8.x4.shared.b16 {%0,%1,%2,%3}, [%4];"
        : "=r"(r0), "=r"(r1), "=r"(r2), "=r"(r3)
        : "r"(addr));
}

// ---------------- neighbor-map transpose ------------------------------------
__global__ __launch_bounds__(256) void transpose_nm(const int* __restrict__ nm) {
    __shared__ int tb[256 * KVOL];
    const int base = blockIdx.x * 256;
    const int nrows = min(256, NSITES - base);
    const int n = nrows * KVOL;
    const long long start = (long long)base * KVOL;
    for (int i = threadIdx.x; i < n; i += 256) tb[i] = nm[start + i];
    __syncthreads();
    const int t = threadIdx.x;
    if (base + t < NSITES) {
#pragma unroll
        for (int k = 0; k < KVOL; k++)
            d_nmT[(size_t)k * NSITES + base + t] = tb[t * KVOL + k];
    }
}

// ---------------- feats -> half ---------------------------------------------
__global__ __launch_bounds__(256) void prep_x(const float* __restrict__ X) {
    const long long i = (long long)blockIdx.x * 256 + threadIdx.x;  // float4 idx
    const float4 v = reinterpret_cast<const float4*>(X)[i];
    __half2* o = reinterpret_cast<__half2*>(d_xh);
    o[2 * i + 0] = __floats2half2_rn(v.x, v.y);
    o[2 * i + 1] = __floats2half2_rn(v.z, v.w);
}

// ---------------- weight transpose -> half ----------------------------------
// W[k][cin][cout] -> WT[k][cout][cin] half
__global__ void prep_w(const float* __restrict__ W, __half* __restrict__ dst,
                       int cin) {
    const int k = blockIdx.x;
    for (int e = threadIdx.x; e < cin * 32; e += 256) {
        const int i = e / 32;
        const int c = e % 32;
        dst[((size_t)k * 32 + c) * cin + i] =
            __float2half_rn(W[((size_t)k * cin + i) * 32 + c]);
    }
}

// ---------------- fp16 mma gather-conv --------------------------------------
// 256 thr / 8 warps; warp w: one m16 tile (16 sites) x 32 couts.
// 4-stage cp.async ring, depth-3 prefetch, idx for k+3 loaded BEFORE the wait
// (latency hidden under wait+MMA), single barrier per iteration (issue writes
// stage (k-1)&3 whose readers finished before this iteration's top barrier).
// OH=1: store half (conv1), OH=0: store float (conv2).
template <int CIN, int OH>
__global__ __launch_bounds__(256) void conv_mma(const __half* __restrict__ X,
                                                const __half* __restrict__ WT,
                                                void* __restrict__ Yv) {
    constexpr int NK = CIN / 16;         // K-steps per offset (2 or 1)
    constexpr int CHA = CIN / 8;         // 16B chunks per row (4 or 2)
    constexpr int STR = CIN + 8;         // padded row stride (halfs)
    constexpr int STRB = STR * 2;        // bytes
    constexpr int STAGE = 160 * STR;     // halfs per stage (128 A + 32 B rows)
    constexpr int IDXN = (128 * CHA + 255) / 256;  // gather ops per thread

    extern __shared__ __half smem[];
    float* const red = reinterpret_cast<float*>(smem);  // reused post-loop

    const int t = threadIdx.x;
    const int w = t >> 5;     // 0..7
    const int lane = t & 31;
    const int g = lane >> 2;  // groupID
    const int ti = lane & 3;  // thread-in-group
    const int siteBase = blockIdx.x * MTILE;

    // ldmatrix per-lane base offsets (bytes)
    const int lr = lane & 7;
    const int sel = lane >> 3;
    const uint32_t aoff =
        (uint32_t)((w * 16 + (sel & 1) * 8 + lr) * STRB + ((sel & 2) ? 16 : 0));
    const uint32_t boff =
        (uint32_t)((((sel >> 1) & 1) * 8 + lr) * STRB + (sel & 1) * 16);

    // coalesced idx loads from transposed map (1 line per warp)
    auto load_idx = [&](int k, int* nidx) {
        const int* nmk = d_nmT + (size_t)k * NSITES;
#pragma unroll
        for (int i = 0; i < IDXN; i++) {
            const int row = (i * 256 + t) / CHA;
            const int gsite = siteBase + row;
            nidx[i] = (gsite < NSITES) ? __ldg(nmk + gsite) : -1;
        }
    };
    auto do_issue = [&](int k, int s, const int* nidx) {
        __half* const As = smem + s * STAGE;
        __half* const Bs = As + 128 * STR;
        const __half* wsrc = WT + (size_t)k * CIN * 32;
        if (t < 32 * CHA) {
            const int row = t / CHA;
            const int ch = t % CHA;
            cp16(s2u(Bs + row * STR + ch * 8), wsrc + t * 8, 16);
        }
#pragma unroll
        for (int i = 0; i < IDXN; i++) {
            const int f = i * 256 + t;
            const int row = f / CHA;
            const int ch = f % CHA;
            const int idx = nidx[i];
            const __half* src =
                X + ((idx >= 0) ? (size_t)idx * CIN : 0) + ch * 8;
            cp16(s2u(As + row * STR + ch * 8), src, (idx >= 0) ? 16u : 0u);
        }
    };

    float acc[4][4];
#pragma unroll
    for (int n = 0; n < 4; n++)
#pragma unroll
        for (int r = 0; r < 4; r++) acc[n][r] = 0.f;

    {
        int pidx[IDXN];
        load_idx(0, pidx);
        do_issue(0, 0, pidx);
        cp_commit();
        load_idx(1, pidx);
        do_issue(1, 1, pidx);
        cp_commit();
        load_idx(2, pidx);
        do_issue(2, 2, pidx);
        cp_commit();
    }

#pragma unroll 1
    for (int k = 0; k < KVOL; k++) {
        int nidx[IDXN];
        if (k + 3 < KVOL) load_idx(k + 3, nidx);  // hidden under wait + MMA
        cp_wait<2>();  // retires group k (uniform dummy commits)
        __syncthreads();

        const __half* As = smem + (k & 3) * STAGE;
        const uint32_t abase = s2u(As) + aoff;
        const uint32_t bbase = s2u(As + 128 * STR) + boff;
#pragma unroll
        for (int ks = 0; ks < NK; ks++) {
            uint32_t bf[4][2];
            ldsm4(bf[0][0], bf[0][1], bf[1][0], bf[1][1],
                  bbase + (uint32_t)(ks * 32));
            ldsm4(bf[2][0], bf[2][1], bf[3][0], bf[3][1],
                  bbase + (uint32_t)(16 * STRB + ks * 32));
            uint32_t a0, a1, a2, a3;
            ldsm4(a0, a1, a2, a3, abase + (uint32_t)(ks * 32));
#pragma unroll
            for (int n = 0; n < 4; n++)
                mma_f16(acc[n], a0, a1, a2, a3, bf[n][0], bf[n][1]);
        }
        // Single barrier per iteration: do_issue writes stage (k+3)&3 =
        // (k-1)&3; its last readers (iter k-1 ldmatrix) finished before this
        // iteration's top barrier, so no WAR hazard.
        if (k + 3 < KVOL) do_issue(k + 3, (k + 3) & 3, nidx);
        cp_commit();  // possibly-empty group keeps wait<2> ledger exact
    }

    // ---- store: thread holds rows {w*16+g, +8}, cols {n*8+2ti, +1} ----
#pragma unroll
    for (int rr = 0; rr < 2; rr++) {
        const int row = w * 16 + rr * 8 + g;
        const int site = siteBase + row;
        if (site < NSITES) {
            if (OH) {
                __half* yr = (__half*)Yv + (size_t)site * 32 + 2 * ti;
#pragma unroll
                for (int n = 0; n < 4; n++)
                    *reinterpret_cast<__half2*>(yr + n * 8) =
                        __floats2half2_rn(acc[n][rr * 2], acc[n][rr * 2 + 1]);
            } else {
                float* yr = (float*)Yv + (size_t)site * 32 + 2 * ti;
#pragma unroll
                for (int n = 0; n < 4; n++)
                    *reinterpret_cast<float2*>(yr + n * 8) =
                        make_float2(acc[n][rr * 2], acc[n][rr * 2 + 1]);
            }
        }
    }

    // ---- BN partial stats (tail rows zero by construction) ----
    float s[8], q[8];
#pragma unroll
    for (int i = 0; i < 8; i++) {
        s[i] = 0.f;
        q[i] = 0.f;
    }
#pragma unroll
    for (int n = 0; n < 4; n++)
#pragma unroll
        for (int rr = 0; rr < 2; rr++)
#pragma unroll
            for (int e = 0; e < 2; e++) {
                const float v = acc[n][rr * 2 + e];
                s[n * 2 + e] += v;
                q[n * 2 + e] += v * v;
            }
#pragma unroll
    for (int i = 0; i < 8; i++) {
#pragma unroll
        for (int o = 4; o <= 16; o <<= 1) {
            s[i] += __shfl_xor_sync(0xffffffffu, s[i], o);
            q[i] += __shfl_xor_sync(0xffffffffu, q[i], o);
        }
    }
    __syncthreads();  // stage smem free for reduction
    if (g == 0) {
#pragma unroll
        for (int i = 0; i < 8; i++) {
            const int col = (i / 2) * 8 + 2 * ti + (i % 2);
            red[w * 64 + col] = s[i];
            red[w * 64 + 32 + col] = q[i];
        }
    }
    __syncthreads();
    if (t < 64) {
        float ss = 0.f;
#pragma unroll
        for (int wi = 0; wi < 8; wi++) ss += red[wi * 64 + t];
        d_part[(size_t)blockIdx.x * 64 + t] = ss;
    }
}

// ---------------- finalize BN stats -> scale/bias --------------------------
__global__ void finalize_kernel(const float* __restrict__ gamma,
                                const float* __restrict__ beta,
                                float* __restrict__ sb, int nb) {
    const int c = blockIdx.x;  // 0..31
    float s = 0.f, q = 0.f;
    for (int b = threadIdx.x; b < nb; b += 256) {
        s += d_part[(size_t)b * 64 + c];
        q += d_part[(size_t)b * 64 + 32 + c];
    }
    __shared__ float ss[8], qs[8];
    const int lane = threadIdx.x & 31;
    const int wrp = threadIdx.x >> 5;
#pragma unroll
    for (int o = 16; o > 0; o >>= 1) {
        s += __shfl_down_sync(0xffffffffu, s, o);
        q += __shfl_down_sync(0xffffffffu, q, o);
    }
    if (lane == 0) {
        ss[wrp] = s;
        qs[wrp] = q;
    }
    __syncthreads();
    if (threadIdx.x == 0) {
        float S = 0.f, Q = 0.f;
#pragma unroll
        for (int w = 0; w < 8; w++) {
            S += ss[w];
            Q += qs[w];
        }
        const float inv_n = 1.0f / (float)NSITES;
        float mean = S * inv_n;
        float var = Q * inv_n - mean * mean;
        float scale = gamma[c] * rsqrtf(var + EPSV);
        sb[c] = scale;
        sb[32 + c] = beta[c] - mean * scale;
    }
}

// ---------------- BN + ReLU on half, in place (conv1 -> conv2 input) --------
__global__ __launch_bounds__(256) void bnrelu_h_kernel(
    __half* __restrict__ HY, const float* __restrict__ sb) {
    __shared__ float sc[32], bi[32];
    if (threadIdx.x < 32) {
        sc[threadIdx.x] = sb[threadIdx.x];
        bi[threadIdx.x] = sb[32 + threadIdx.x];
    }
    __syncthreads();
    const long long i = (long long)blockIdx.x * 256 + threadIdx.x;  // uint4 idx
    uint4 v = reinterpret_cast<uint4*>(HY)[i];
    const int c0 = (int)((i * 8) & 31);
    uint32_t* vw = reinterpret_cast<uint32_t*>(&v);
#pragma unroll
    for (int j = 0; j < 4; j++) {
        __half2 h = *reinterpret_cast<__half2*>(&vw[j]);
        float2 f = __half22float2(h);
        f.x = fmaxf(0.f, fmaf(f.x, sc[c0 + 2 * j], bi[c0 + 2 * j]));
        f.y = fmaxf(0.f, fmaf(f.y, sc[c0 + 2 * j + 1], bi[c0 + 2 * j + 1]));
        h = __floats2half2_rn(f.x, f.y);
        vw[j] = *reinterpret_cast<uint32_t*>(&h);
    }
    reinterpret_cast<uint4*>(HY)[i] = v;
}

// ---------------- BN + ReLU on fp32, in place (final output) ----------------
__global__ __launch_bounds__(256) void bnrelu_f_kernel(
    float* __restrict__ Y, const float* __restrict__ sb) {
    __shared__ float sc[32], bi[32];
    if (threadIdx.x < 32) {
        sc[threadIdx.x] = sb[threadIdx.x];
        bi[threadIdx.x] = sb[32 + threadIdx.x];
    }
    __syncthreads();
    const long long i = (long long)blockIdx.x * 256 + threadIdx.x;  // float4 idx
    float4 v = reinterpret_cast<const float4*>(Y)[i];
    const int c0 = (int)((i * 4) & 31);
    v.x = fmaxf(0.f, fmaf(v.x, sc[c0 + 0], bi[c0 + 0]));
    v.y = fmaxf(0.f, fmaf(v.y, sc[c0 + 1], bi[c0 + 1]));
    v.z = fmaxf(0.f, fmaf(v.z, sc[c0 + 2], bi[c0 + 2]));
    v.w = fmaxf(0.f, fmaf(v.w, sc[c0 + 3], bi[c0 + 3]));
    reinterpret_cast<float4*>(Y)[i] = v;
}

// ---------------- launch ----------------------------------------------------
extern "C" void kernel_launch(void* const* d_in, const int* in_sizes, int n_in,
                              void* d_out, int out_size) {
    const float* feats = (const float*)d_in[0];
    const int* nm = (const int*)d_in[1];
    const float* W1 = (const float*)d_in[2];
    const float* gamma1 = (const float*)d_in[3];
    const float* beta1 = (const float*)d_in[4];
    const float* W2 = (const float*)d_in[5];
    const float* gamma2 = (const float*)d_in[6];
    const float* beta2 = (const float*)d_in[7];
    float* out = (float*)d_out;

    const int smem1 = NST * 160 * (16 + 8) * 2;  // 30720 B
    const int smem2 = NST * 160 * (32 + 8) * 2;  // 51200 B
    cudaFuncSetAttribute(conv_mma<16, 1>,
                         cudaFuncAttributeMaxDynamicSharedMemorySize, smem1);
    cudaFuncSetAttribute(conv_mma<32, 0>,
                         cudaFuncAttributeMaxDynamicSharedMemorySize, smem2);

    void* p;
    cudaGetSymbolAddress(&p, d_h1h);
    __half* h1h = (__half*)p;
    cudaGetSymbolAddress(&p, d_xh);
    __half* xh = (__half*)p;
    cudaGetSymbolAddress(&p, d_wT1);
    __half* wT1 = (__half*)p;
    cudaGetSymbolAddress(&p, d_wT2);
    __half* wT2 = (__half*)p;
    cudaGetSymbolAddress(&p, d_sb1);
    float* sb1 = (float*)p;
    cudaGetSymbolAddress(&p, d_sb2);
    float* sb2 = (float*)p;

    const int ewf_blocks = (int)(((long long)NSITES * 32 / 4) / 256);  // 31250
    const int ewh_blocks = (int)(((long long)NSITES * 32 / 8) / 256);  // 15625
    const int px_blocks = (int)(((long long)NSITES * 16 / 4) / 256);   // 15625
    const int tr_blocks = (NSITES + 255) / 256;                        // 3907

    transpose_nm<<<tr_blocks, 256>>>(nm);
    prep_x<<<px_blocks, 256>>>(feats);
    prep_w<<<KVOL, 256>>>(W1, wT1, 16);
    prep_w<<<KVOL, 256>>>(W2, wT2, 32);

    conv_mma<16, 1><<<NTILES, 256, smem1>>>(xh, wT1, h1h);
    finalize_kernel<<<32, 256>>>(gamma1, beta1, sb1, NTILES);
    bnrelu_h_kernel<<<ewh_blocks, 256>>>(h1h, sb1);

    conv_mma<32, 0><<<NTILES, 256, smem2>>>(h1h, wT2, out);
    finalize_kernel<<<32, 256>>>(gamma2, beta2, sb2, NTILES);
    bnrelu_f_kernel<<<ewf_blocks, 256>>>(out, sb2);
}